// round 15
// baseline (speedup 1.0000x reference)
#include <cuda_runtime.h>
#include <cuda_bf16.h>
#include <math.h>
#include <stdint.h>

#define T_LEN   64
#define BATCH   1024
#define VOCAB   128
#define HID     512
#define G4      2048
#define IMGFEAT 3600
#define KPAD    3648

// ---------------- helpers ----------------
__device__ __forceinline__ void cp16(uint32_t dst, const void* src) {
    size_t g = __cvta_generic_to_global(src);
    asm volatile("cp.async.cg.shared.global [%0], [%1], 16;" :: "r"(dst), "l"(g));
}
#define CP_COMMIT() asm volatile("cp.async.commit_group;" ::: "memory")
#define CP_WAIT(n)  asm volatile("cp.async.wait_group %0;" :: "n"(n) : "memory")

__device__ __forceinline__ uint32_t smem_u32(const void* p) {
    uint32_t a;
    asm("{ .reg .u64 t; cvta.to.shared.u64 t, %1; cvt.u32.u64 %0, t; }" : "=r"(a) : "l"(p));
    return a;
}

__device__ __forceinline__ float ftanh(float x) {
    float y;
    asm("tanh.approx.f32 %0, %1;" : "=f"(y) : "f"(x));
    return y;
}
__device__ __forceinline__ float fsig(float x) {
    return 0.5f * ftanh(0.5f * x) + 0.5f;
}

__device__ __forceinline__ uint32_t bf2_as_u32(__nv_bfloat162 v) {
    uint32_t u;
    memcpy(&u, &v, 4);
    return u;
}
__device__ __forceinline__ float2 u32_as_f2(uint32_t u) {
    __nv_bfloat162 v;
    memcpy(&v, &u, 4);
    return __bfloat1622float2(v);
}

__device__ __forceinline__ void mma_bf16(float c[4],
                                         uint32_t a0, uint32_t a1, uint32_t a2, uint32_t a3,
                                         uint32_t b0, uint32_t b1) {
    asm volatile(
        "mma.sync.aligned.m16n8k16.row.col.f32.bf16.bf16.f32 "
        "{%0,%1,%2,%3}, {%4,%5,%6,%7}, {%8,%9}, {%0,%1,%2,%3};"
        : "+f"(c[0]), "+f"(c[1]), "+f"(c[2]), "+f"(c[3])
        : "r"(a0), "r"(a1), "r"(a2), "r"(a3), "r"(b0), "r"(b1));
}

// ---- TMA 1D bulk copy + mbarrier ----
#define MBAR_INIT(mb, c)  asm volatile("mbarrier.init.shared.b64 [%0], %1;" :: "r"(mb), "r"(c) : "memory")
#define MBAR_EXPECT_TX(mb, bytes) \
    asm volatile("mbarrier.arrive.expect_tx.shared.b64 _, [%0], %1;" :: "r"(mb), "r"(bytes) : "memory")

__device__ __forceinline__ void bulk_g2s(uint32_t dst, const void* src, uint32_t bytes, uint32_t mbar) {
    asm volatile("cp.async.bulk.shared::cluster.global.mbarrier::complete_tx::bytes [%0], [%1], %2, [%3];"
                 :: "r"(dst), "l"(__cvta_generic_to_global((void*)src)), "r"(bytes), "r"(mbar) : "memory");
}

#define MBAR_WAIT(mb, par) do {                                                   \
    uint32_t _m = (mb), _p = (par), _d;                                           \
    asm volatile("{\n\t.reg .pred p;\n\t"                                         \
        "mbarrier.try_wait.parity.acquire.cta.shared::cta.b64 p, [%1], %2;\n\t"   \
        "selp.b32 %0, 1, 0, p;\n\t}" : "=r"(_d) : "r"(_m), "r"(_p) : "memory");   \
    if (!_d) {                                                                    \
        asm volatile("{\n\t.reg .pred P1;\n\t"                                    \
        "W_%=:\n\t"                                                               \
        "mbarrier.try_wait.parity.acquire.cta.shared::cta.b64 P1, [%0], %1, 0x989680;\n\t" \
        "@P1 bra.uni D_%=;\n\tbra.uni W_%=;\n\tD_%=:\n\t}"                        \
        :: "r"(_m), "r"(_p) : "memory");                                          \
    }                                                                             \
} while (0)

// ---------------- scratch ----------------
__device__ __nv_bfloat16 g_a2b[(size_t)BATCH * KPAD];
__device__ float g_e [BATCH * HID];
__device__ __nv_bfloat16 g_wt[(size_t)G4 * HID];
__device__ __nv_bfloat16 g_xt[(size_t)G4 * VOCAB];
__device__ __nv_bfloat16 g_owtb[VOCAB * HID];
__device__ __nv_bfloat16 g_fwt[(size_t)HID * KPAD];
__device__ __nv_bfloat16 g_xb[(size_t)T_LEN * BATCH * VOCAB];
__device__ float g_b4[G4];
__device__ __nv_bfloat16 g_hsb[(size_t)T_LEN * BATCH * HID];
__device__ uint32_t g_hswz[(size_t)T_LEN * 8 * 8 * 4096];
__device__ uint32_t g_xgt [(size_t)T_LEN * 8 * 16 * 8192];
__device__ unsigned g_barf[64];   // per (mg, kchunk) producer flags

// ---------------- prep_all ----------------
#define PREP_BLOCKS 19561
__global__ void __launch_bounds__(256)
prep_all(const float* __restrict__ inp,
         const float* __restrict__ hhw, const float* __restrict__ xhw,
         const float* __restrict__ ow,  const float* __restrict__ fw,
         const float* __restrict__ xhb, const float* __restrict__ hhb) {
    const int blk = blockIdx.x, tid = threadIdx.x;
    if (blk < 16384) {
        int i = blk * 256 + tid;
        const float2* s = (const float2*)inp;
        ((__nv_bfloat162*)g_xb)[i] = __float22bfloat162_rn(s[i]);
        return;
    }
    __shared__ float ts[32][33];
    int x = tid & 31;
    int yr = tid >> 5;
    if (blk < 17408) {
        int b = blk - 16384;
        int bn = (b & 63) * 32, bk = (b >> 6) * 32;
#pragma unroll
        for (int i = 0; i < 32; i += 8)
            ts[yr + i][x] = hhw[(size_t)(bk + yr + i) * G4 + bn + x];
        __syncthreads();
#pragma unroll
        for (int i = 0; i < 32; i += 8)
            g_wt[(size_t)(bn + yr + i) * HID + bk + x] = __float2bfloat16_rn(ts[x][yr + i]);
    } else if (blk < 17664) {
        int b = blk - 17408;
        int bn = (b & 63) * 32, bk = (b >> 6) * 32;
#pragma unroll
        for (int i = 0; i < 32; i += 8)
            ts[yr + i][x] = xhw[(size_t)(bk + yr + i) * G4 + bn + x];
        __syncthreads();
#pragma unroll
        for (int i = 0; i < 32; i += 8)
            g_xt[(size_t)(bn + yr + i) * VOCAB + bk + x] = __float2bfloat16_rn(ts[x][yr + i]);
    } else if (blk < 17728) {
        int b = blk - 17664;
        int bn = (b & 3) * 32, bk = (b >> 2) * 32;
#pragma unroll
        for (int i = 0; i < 32; i += 8)
            ts[yr + i][x] = ow[(size_t)(bk + yr + i) * VOCAB + bn + x];
        __syncthreads();
#pragma unroll
        for (int i = 0; i < 32; i += 8)
            g_owtb[(size_t)(bn + yr + i) * HID + bk + x] = __float2bfloat16_rn(ts[x][yr + i]);
    } else if (blk < 19552) {
        int b = blk - 17728;
        int bn = (b & 15) * 32, bk = (b >> 4) * 32;
#pragma unroll
        for (int i = 0; i < 32; i += 8) {
            int k = bk + yr + i;
            ts[yr + i][x] = (k < IMGFEAT) ? fw[(size_t)k * HID + bn + x] : 0.f;
        }
        __syncthreads();
#pragma unroll
        for (int i = 0; i < 32; i += 8)
            g_fwt[(size_t)(bn + yr + i) * KPAD + bk + x] = __float2bfloat16_rn(ts[x][yr + i]);
    } else if (blk < 19560) {
        int i = (blk - 19552) * 256 + tid;
        g_b4[i] = xhb[i] + hhb[i];
    } else {
        if (tid < 64) g_barf[tid] = 0;
    }
}

// ---------------- fused CNN ----------------
#define A1_CH  1156
#define SM_IMG 0
#define SM_A1  4356
#define SM_W1  13604
#define SM_B1  13676
#define SM_W2  13684
#define SM_B2  16884
#define CNN_SMEM (16900 * 4)

__global__ void __launch_bounds__(256, 1)
cnn_fused(const float* __restrict__ img,
          const float* __restrict__ c1w, const float* __restrict__ c1b,
          const float* __restrict__ c2w, const float* __restrict__ c2b) {
    extern __shared__ float sf[];
    const int tid = threadIdx.x;
    const int bb = blockIdx.x;

    for (int i = tid; i < SM_A1 + 8 * A1_CH; i += 256) sf[i] = 0.f;
    for (int i = tid; i < 72; i += 256) sf[SM_W1 + i] = c1w[i];
    if (tid < 8) sf[SM_B1 + tid] = c1b[tid];
    for (int i = tid; i < 3200; i += 256) sf[SM_W2 + i] = c2w[i];
    if (tid < 16) sf[SM_B2 + tid] = c2b[tid];
    __syncthreads();

    const float* im = img + (size_t)bb * 4096;
    for (int i = tid; i < 1024; i += 256) {
        int r = i >> 4, c = (i & 15) * 4;
        float4 v = *(const float4*)&im[r * 64 + c];
        float* d = &sf[SM_IMG + (r + 1) * 66 + c + 1];
        d[0] = v.x; d[1] = v.y; d[2] = v.z; d[3] = v.w;
    }
    __syncthreads();

#pragma unroll
    for (int j = 0; j < 32; j++) {
        int idx = tid + j * 256;
        int px = idx & 31, py = (idx >> 5) & 31, oc = idx >> 10;
        const float* w = &sf[SM_W1 + oc * 9];
        float bias = sf[SM_B1 + oc];
        float m = -1e30f;
#pragma unroll
        for (int dy = 0; dy < 2; dy++)
#pragma unroll
        for (int dx = 0; dx < 2; dx++) {
            float acc = bias;
#pragma unroll
            for (int ky = 0; ky < 3; ky++)
#pragma unroll
            for (int kx = 0; kx < 3; kx++)
                acc += sf[SM_IMG + (2 * py + dy + ky) * 66 + 2 * px + dx + kx] * w[ky * 3 + kx];
            m = fmaxf(m, fmaxf(acc, 0.f));
        }
        sf[SM_A1 + oc * A1_CH + (py + 1) * 34 + px + 1] = m;
    }
    __syncthreads();

    if (tid < 240) {
        int oc = tid / 15, py = tid % 15;
        float bias = sf[SM_B2 + oc];
        float m[15];
#pragma unroll
        for (int p = 0; p < 15; p++) m[p] = -1e30f;
#pragma unroll
        for (int dy = 0; dy < 2; dy++) {
            float conv[30];
#pragma unroll
            for (int ox = 0; ox < 30; ox++) conv[ox] = bias;
            for (int ic = 0; ic < 8; ic++) {
#pragma unroll
                for (int ky = 0; ky < 5; ky++) {
                    const float* rp = &sf[SM_A1 + ic * A1_CH + (2 * py + dy + ky) * 34];
                    float r[34];
#pragma unroll
                    for (int xx = 0; xx < 34; xx++) r[xx] = rp[xx];
                    const float* wp = &sf[SM_W2 + (oc * 8 + ic) * 25 + ky * 5];
#pragma unroll
                    for (int kx = 0; kx < 5; kx++) {
                        float w = wp[kx];
#pragma unroll
                        for (int ox = 0; ox < 30; ox++) conv[ox] += r[ox + kx] * w;
                    }
                }
            }
#pragma unroll
            for (int p = 0; p < 15; p++) {
                float c0 = fmaxf(conv[2 * p], 0.f), c1 = fmaxf(conv[2 * p + 1], 0.f);
                m[p] = fmaxf(m[p], fmaxf(c0, c1));
            }
        }
        size_t base = (size_t)bb * KPAD + oc * 225 + py * 15;
#pragma unroll
        for (int p = 0; p < 15; p++) g_a2b[base + p] = __float2bfloat16_rn(m[p]);
    }
}

// ---------------- gemm_pre: imgfc (blk<64) + xg (blk>=64) ----------------
#define IF_AS 36
#define IF_ABUF (128 * IF_AS)
#define IF_BBUF (64 * IF_AS)
#define XG_AS 68
#define GP_SMEM (2 * 128 * XG_AS * 4)

__global__ void __launch_bounds__(256, 1)
gemm_pre(const float* __restrict__ fb) {
    extern __shared__ uint32_t smu[];
    const int tid = threadIdx.x, lane = tid & 31, wid = tid >> 5;
    const int gq = lane >> 2, tq = lane & 3;

    if (blockIdx.x < 64) {
        uint32_t* As = smu;
        uint32_t* Bs = smu + 2 * IF_ABUF;
        const uint32_t a_u = smem_u32(As), b_u = smem_u32(Bs);
        const int wm = wid & 3, wn = wid >> 2;
        const int bm = (blockIdx.x >> 3) * 128, bn = (blockIdx.x & 7) * 64;

        float acc[2][4][4] = {};
        auto load_chunk = [&](int k0, int p) {
#pragma unroll
            for (int j = 0; j < 4; j++) {
                int idx = tid + j * 256;
                int r = idx >> 3, c4 = idx & 7;
                cp16(a_u + p * IF_ABUF * 4 + r * (IF_AS * 4) + c4 * 16,
                     g_a2b + (size_t)(bm + r) * KPAD + k0 + c4 * 8);
            }
#pragma unroll
            for (int j = 0; j < 2; j++) {
                int idx = tid + j * 256;
                int r = idx >> 3, c4 = idx & 7;
                cp16(b_u + p * IF_BBUF * 4 + r * (IF_AS * 4) + c4 * 16,
                     g_fwt + (size_t)(bn + r) * KPAD + k0 + c4 * 8);
            }
            CP_COMMIT();
        };

        const int NCH = KPAD / 64;
        load_chunk(0, 0);
        for (int c = 0; c < NCH; c++) {
            if (c + 1 < NCH) { load_chunk((c + 1) * 64, (c + 1) & 1); CP_WAIT(1); }
            else             { CP_WAIT(0); }
            __syncthreads();
            const uint32_t* Ab = As + (c & 1) * IF_ABUF;
            const uint32_t* Bb = Bs + (c & 1) * IF_BBUF;
#pragma unroll
            for (int ks = 0; ks < 4; ks++) {
                uint32_t afr[2][4];
#pragma unroll
                for (int mt = 0; mt < 2; mt++) {
                    int r0 = wm * 32 + mt * 16 + gq;
                    afr[mt][0] = Ab[(r0    ) * IF_AS + ks * 8 + tq    ];
                    afr[mt][1] = Ab[(r0 + 8) * IF_AS + ks * 8 + tq    ];
                    afr[mt][2] = Ab[(r0    ) * IF_AS + ks * 8 + tq + 4];
                    afr[mt][3] = Ab[(r0 + 8) * IF_AS + ks * 8 + tq + 4];
                }
#pragma unroll
                for (int nt = 0; nt < 4; nt++) {
                    int nrow = wn * 32 + nt * 8 + gq;
                    uint32_t b0 = Bb[nrow * IF_AS + ks * 8 + tq    ];
                    uint32_t b1 = Bb[nrow * IF_AS + ks * 8 + tq + 4];
#pragma unroll
                    for (int mt = 0; mt < 2; mt++)
                        mma_bf16(acc[mt][nt], afr[mt][0], afr[mt][1], afr[mt][2], afr[mt][3], b0, b1);
                }
            }
            __syncthreads();
        }

#pragma unroll
        for (int mt = 0; mt < 2; mt++)
#pragma unroll
            for (int nt = 0; nt < 4; nt++) {
                int n = bn + wn * 32 + nt * 8 + tq * 2;
                int m = bm + wm * 32 + mt * 16 + gq;
                float b0 = fb[n], b1 = fb[n + 1];
                g_e[(size_t)m * HID + n]           = fmaxf(acc[mt][nt][0] + b0, 0.f);
                g_e[(size_t)m * HID + n + 1]       = fmaxf(acc[mt][nt][1] + b1, 0.f);
                g_e[(size_t)(m + 8) * HID + n]     = fmaxf(acc[mt][nt][2] + b0, 0.f);
                g_e[(size_t)(m + 8) * HID + n + 1] = fmaxf(acc[mt][nt][3] + b1, 0.f);
            }
        return;
    }

    {
        uint32_t* As = smu;
        uint32_t* Bs = smu + 128 * XG_AS;
        const uint32_t a_u = smem_u32(As), b_u = smem_u32(Bs);
        const int wm = wid & 3, wn = wid >> 2;
        const int bb = (int)blockIdx.x - 64;
        const int bm = (bb >> 4) * 128, bn = (bb & 15) * 128;

#pragma unroll
        for (int j = 0; j < 8; j++) {
            int idx = tid + j * 256;
            int r = idx >> 4, c4 = idx & 15;
            cp16(a_u + r * (XG_AS * 4) + c4 * 16, g_xb + (size_t)(bm + r) * VOCAB + c4 * 8);
        }
#pragma unroll
        for (int j = 0; j < 8; j++) {
            int idx = tid + j * 256;
            int r = idx >> 4, c4 = idx & 15;
            cp16(b_u + r * (XG_AS * 4) + c4 * 16, g_xt + (size_t)(bn + r) * VOCAB + c4 * 8);
        }
        CP_COMMIT(); CP_WAIT(0);
        __syncthreads();

        float acc[2][8][4] = {};
#pragma unroll
        for (int ks = 0; ks < 8; ks++) {
            uint32_t afr[2][4];
#pragma unroll
            for (int mt = 0; mt < 2; mt++) {
                int r0 = wm * 32 + mt * 16 + gq;
                afr[mt][0] = As[(r0    ) * XG_AS + ks * 8 + tq    ];
                afr[mt][1] = As[(r0 + 8) * XG_AS + ks * 8 + tq    ];
                afr[mt][2] = As[(r0    ) * XG_AS + ks * 8 + tq + 4];
                afr[mt][3] = As[(r0 + 8) * XG_AS + ks * 8 + tq + 4];
            }
#pragma unroll
            for (int nt = 0; nt < 8; nt++) {
                int nrow = wn * 64 + nt * 8 + gq;
                uint32_t b0 = Bs[nrow * XG_AS + ks * 8 + tq    ];
                uint32_t b1 = Bs[nrow * XG_AS + ks * 8 + tq + 4];
#pragma unroll
                for (int mt = 0; mt < 2; mt++)
                    mma_bf16(acc[mt][nt], afr[mt][0], afr[mt][1], afr[mt][2], afr[mt][3], b0, b1);
            }
        }
        __syncthreads();

        uint32_t* St = smu;
        const int ns0 = (bn & 511) >> 5;
        const int g = bn >> 9;
#pragma unroll
        for (int mt = 0; mt < 2; mt++)
#pragma unroll
            for (int nt = 0; nt < 8; nt++) {
                int r = wm * 32 + mt * 16 + gq;
                int n = wn * 64 + nt * 8 + tq * 2;
                int ns_l = n >> 5;
                int jcol = (n & 31) >> 1;
                St[r * 64 + ns_l * 16 + jcol] =
                    bf2_as_u32(__float22bfloat162_rn(make_float2(acc[mt][nt][0], acc[mt][nt][1])));
                St[(r + 8) * 64 + ns_l * 16 + jcol] =
                    bf2_as_u32(__float22bfloat162_rn(make_float2(acc[mt][nt][2], acc[mt][nt][3])));
            }
        __syncthreads();

        const int t = bm >> 10, mg = (bm >> 7) & 7;
        const size_t blkbase = (size_t)(t * 8 + mg) * 16;
        for (int i = tid; i < 2048; i += 256) {
            int r = i >> 4, q = i & 15;
            int ns_l = q >> 2, k = q & 3;
            int kk = k ^ (r & 3);
            int gg = g ^ ((r & 4) >> 2);
            uint4 v = *(const uint4*)&St[r * 64 + ns_l * 16 + k * 4];
            *(uint4*)&g_xgt[(blkbase + ns0 + ns_l) * 8192 + r * 64 + gg * 16 + kk * 4] = v;
        }
    }
}

// ---------------- persistent LSTM: per-chunk producer flags ----------------
#define LSTM_SMEM (57856 * 4 + 48)

__global__ void __launch_bounds__(512, 1)
lstm_persistent() {
    extern __shared__ uint32_t S[];
    uint32_t* Bhh = S;
    uint32_t* Xgs = S + 33280;
    uint32_t* Abuf = S + 41472;
    const uint32_t xg_u = smem_u32(S + 33280);
    const uint32_t a_u0 = smem_u32(S + 41472);
    const uint32_t mb_u = smem_u32(S + 57856);

    const int tid = threadIdx.x, lane = tid & 31, wid = tid >> 5;
    const int wm = wid & 3, wn = wid >> 2;
    const int gq = lane >> 2, tq = lane & 3;
    const int blk = blockIdx.x;
    const int mg = blk >> 4, ns = blk & 15;
    const int m0 = mg * 128, n0 = ns * 32;
    const int kch = ns >> 1;

    for (int i = tid; i < 128 * 64; i += 512) {
        int row = i >> 6, c4 = i & 63;
        int g = row >> 5, n = row & 31;
        *(uint4*)((char*)Bhh + row * (260 * 4) + c4 * 16) =
            *(const uint4*)((const char*)(g_wt + (size_t)(g * HID + n0 + n) * HID) + c4 * 16);
    }
    if (tid == 0) {
#pragma unroll
        for (int s = 0; s < 4; s++) MBAR_INIT(mb_u + s * 8, 1);
        MBAR_INIT(mb_u + 32, 1);
    }

    float creg[2][2][2];
#pragma unroll
    for (int mt = 0; mt < 2; mt++)
#pragma unroll
        for (int h = 0; h < 2; h++) creg[mt][h][0] = creg[mt][h][1] = 0.f;

    __syncthreads();

    const int nn = n0 + wn * 8 + tq * 2;
    const int xr = gq << 2;
    int phA[4] = {0, 0, 0, 0};
    unsigned* myflag = &g_barf[mg * 8 + kch];

    for (int t = 0; t < T_LEN; t++) {
        float acc[4][2][4];
#pragma unroll
        for (int g = 0; g < 4; g++)
#pragma unroll
            for (int mt = 0; mt < 2; mt++)
#pragma unroll
                for (int j = 0; j < 4; j++) acc[g][mt][j] = 0.f;

        const uint32_t* hsrc = g_hswz + (size_t)((t - 1) * 8 + mg) * 8 * 4096;

        // xg bulk depends only on gemm_pre -> issue first
        if (tid == 0) {
            MBAR_EXPECT_TX(mb_u + 32, 32768u);
            bulk_g2s(xg_u, g_xgt + ((size_t)(t * 8 + mg) * 16 + ns) * 8192, 32768u, mb_u + 32);
        }

        if (t > 0) {
            const unsigned tgt = (unsigned)(2 * t);
            if (tid == 0) {
#pragma unroll
                for (int s = 0; s < 3; s++) {
                    unsigned v;
                    do {
                        asm volatile("ld.acquire.gpu.global.u32 %0, [%1];"
                                     : "=r"(v) : "l"(&g_barf[mg * 8 + s]) : "memory");
                    } while (v < tgt);
                    MBAR_EXPECT_TX(mb_u + s * 8, 16384u);
                    bulk_g2s(a_u0 + s * 16384, hsrc + s * 4096, 16384u, mb_u + s * 8);
                }
            }
            for (int c = 0; c < 8; c++) {
                if (c + 3 < 8 && tid == 0) {
                    unsigned v;
                    do {
                        asm volatile("ld.acquire.gpu.global.u32 %0, [%1];"
                                     : "=r"(v) : "l"(&g_barf[mg * 8 + c + 3]) : "memory");
                    } while (v < tgt);
                    int s2 = (c + 3) & 3;
                    MBAR_EXPECT_TX(mb_u + s2 * 8, 16384u);
                    bulk_g2s(a_u0 + s2 * 16384, hsrc + (c + 3) * 4096, 16384u, mb_u + s2 * 8);
                }
                int s = c & 3;
                MBAR_WAIT(mb_u + s * 8, phA[s] & 1);
                phA[s]++;

                const uint32_t* Apk = Abuf + s * 4096;
#pragma unroll
                for (int ks = 0; ks < 4; ks++) {
                    uint32_t afr[2][4];
#pragma unroll
                    for (int mt = 0; mt < 2; mt++) {
                        int r0 = wm * 32 + mt * 16 + gq;
                        afr[mt][0] = Apk[(r0    ) * 32 + ((ks * 8 + tq    ) ^ xr)];
                        afr[mt][1] = Apk[(r0 + 8) * 32 + ((ks * 8 + tq    ) ^ xr)];
                        afr[mt][2] = Apk[(r0    ) * 32 + ((ks * 8 + tq + 4) ^ xr)];
                        afr[mt][3] = Apk[(r0 + 8) * 32 + ((ks * 8 + tq + 4) ^ xr)];
                    }
                    const int kcol = c * 32 + ks * 8;
#pragma unroll
                    for (int g = 0; g < 4; g++) {
                        int nrow = g * 32 + wn * 8 + gq;
                        uint32_t b0 = Bhh[nrow * 260 + kcol + tq    ];
                        uint32_t b1 = Bhh[nrow * 260 + kcol + tq + 4];
#pragma unroll
                        for (int mt = 0; mt < 2; mt++)
                            mma_bf16(acc[g][mt], afr[mt][0], afr[mt][1], afr[mt][2], afr[mt][3], b0, b1);
                    }
                }
                __syncthreads();
            }
        }

        MBAR_WAIT(mb_u + 32, t & 1);

        float2 b4i = *(const float2*)&g_b4[0 * HID + nn];
        float2 b4f = *(const float2*)&g_b4[1 * HID + nn];
        float2 b4g = *(const float2*)&g_b4[2 * HID + nn];
        float2 b4o = *(const float2*)&g_b4[3 * HID + nn];
        __nv_bfloat16* hs_t = g_hsb + (size_t)t * BATCH * HID;
        uint32_t* hwz_t = g_hswz + (size_t)((t * 8 + mg) * 8 + kch) * 4096;
        const int ncol = wn * 4 + tq;
        const int cu = (nn >> 1) & 31;
#pragma unroll
        for (int mt = 0; mt < 2; mt++) {
#pragma unroll
            for (int half = 0; half < 2; half++) {
                int r = wm * 32 + mt * 16 + gq + half * 8;
                int m = m0 + r;
                float2 vi = u32_as_f2(Xgs[r * 64 + ((0 * 16 + ncol) ^ xr)]);
                float2 vf = u32_as_f2(Xgs[r * 64 + ((1 * 16 + ncol) ^ xr)]);
                float2 vg = u32_as_f2(Xgs[r * 64 + ((2 * 16 + ncol) ^ xr)]);
                float2 vo = u32_as_f2(Xgs[r * 64 + ((3 * 16 + ncol) ^ xr)]);
                float2 ev = make_float2(0.f, 0.f);
                if (t == 0) ev = *(const float2*)&g_e[(size_t)m * HID + nn];
                float2 hv;
#pragma unroll
                for (int e = 0; e < 2; e++) {
                    float ee = e ? ev.y : ev.x;
                    float gi = acc[0][mt][half * 2 + e] + (e ? b4i.y : b4i.x) + (e ? vi.y : vi.x) + ee;
                    float gf = acc[1][mt][half * 2 + e] + (e ? b4f.y : b4f.x) + (e ? vf.y : vf.x) + ee;
                    float gg = acc[2][mt][half * 2 + e] + (e ? b4g.y : b4g.x) + (e ? vg.y : vg.x) + ee;
                    float go = acc[3][mt][half * 2 + e] + (e ? b4o.y : b4o.x) + (e ? vo.y : vo.x) + ee;
                    float i_ = fsig(gi);
                    float f_ = fsig(gf);
                    float g_ = ftanh(gg);
                    float o_ = fsig(go);
                    float cn = f_ * creg[mt][half][e] + i_ * g_;
                    creg[mt][half][e] = cn;
                    float hn = o_ * ftanh(cn);
                    if (e) hv.y = hn; else hv.x = hn;
                }
                __nv_bfloat162 hb = __float22bfloat162_rn(hv);
                *(__nv_bfloat162*)&hs_t[(size_t)m * HID + nn] = hb;
                hwz_t[r * 32 + (cu ^ xr)] = bf2_as_u32(hb);
            }
        }

        __syncthreads();
        if (tid == 0 && t + 1 < T_LEN)
            asm volatile("red.release.gpu.global.add.u32 [%0], 1;" :: "l"(myflag) : "memory");
    }
}

// ---------------- out proj (bf16 mma) + fused log_softmax ----------------
#define O_AS 36
#define O_ABUF (64 * O_AS)
#define O_BBUF (128 * O_AS)
#define O_LSOFF (2 * O_ABUF + 2 * O_BBUF)
#define OUT_SMEM ((O_LSOFF + 64 * 132) * 4)
__global__ void __launch_bounds__(256, 1)
out_logsoftmax_b(const float* __restrict__ bias, float* __restrict__ out) {
    extern __shared__ uint32_t smu[];
    uint32_t* As = smu;
    uint32_t* Bs = smu + 2 * O_ABUF;
    float* Ls = (float*)(smu + O_LSOFF);
    const uint32_t a_u = smem_u32(As), b_u = smem_u32(Bs);
    const int tid = threadIdx.x, lane = tid & 31, wid = tid >> 5;
    const int wm = wid & 1, wn = wid >> 1;
    const int gq = lane >> 2, tq = lane & 3;
    const int bm = blockIdx.x * 64;

    float acc[2][4][4] = {};

    auto load_chunk = [&](int k0, int p) {
#pragma unroll
        for (int j = 0; j < 2; j++) {
            int idx = tid + j * 256;
            int r = idx >> 3, c4 = idx & 7;
            cp16(a_u + p * O_ABUF * 4 + r * (O_AS * 4) + c4 * 16,
                 g_hsb + (size_t)(bm + r) * HID + k0 + c4 * 8);
        }
#pragma unroll
        for (int j = 0; j < 4; j++) {
            int idx = tid + j * 256;
            int r = idx >> 3, c4 = idx & 7;
            cp16(b_u + p * O_BBUF * 4 + r * (O_AS * 4) + c4 * 16,
                 g_owtb + (size_t)r * HID + k0 + c4 * 8);
        }
        CP_COMMIT();
    };

    load_chunk(0, 0);
    for (int c = 0; c < 8; c++) {
        if (c + 1 < 8) { load_chunk((c + 1) * 64, (c + 1) & 1); CP_WAIT(1); }
        else           { CP_WAIT(0); }
        __syncthreads();
        const uint32_t* Ab = As + (c & 1) * O_ABUF;
        const uint32_t* Bb = Bs + (c & 1) * O_BBUF;
#pragma unroll
        for (int ks = 0; ks < 4; ks++) {
            uint32_t afr[2][4];
#pragma unroll
            for (int mt = 0; mt < 2; mt++) {
                int r0 = wm * 32 + mt * 16 + gq;
                afr[mt][0] = Ab[(r0    ) * O_AS + ks * 8 + tq    ];
                afr[mt][1] = Ab[(r0 + 8) * O_AS + ks * 8 + tq    ];
                afr[mt][2] = Ab[(r0    ) * O_AS + ks * 8 + tq + 4];
                afr[mt][3] = Ab[(r0 + 8) * O_AS + ks * 8 + tq + 4];
            }
#pragma unroll
            for (int nt = 0; nt < 4; nt++) {
                int nrow = wn * 32 + nt * 8 + gq;
                uint32_t b0 = Bb[nrow * O_AS + ks * 8 + tq    ];
                uint32_t b1 = Bb[nrow * O_AS + ks * 8 + tq + 4];
#pragma unroll
                for (int mt = 0; mt < 2; mt++)
                    mma_bf16(acc[mt][nt], afr[mt][0], afr[mt][1], afr[mt][2], afr[mt][3], b0, b1);
            }
        }
        __syncthreads();
    }

#pragma unroll
    for (int mt = 0; mt < 2; mt++)
#pragma unroll
        for (int nt = 0; nt < 4; nt++) {
            int row = wm * 32 + mt * 16 + gq;
            int col = wn * 32 + nt * 8 + tq * 2;
            float b0 = bias[col], b1 = bias[col + 1];
            Ls[(row    ) * 132 + col    ] = acc[mt][nt][0] + b0;
            Ls[(row    ) * 132 + col + 1] = acc[mt][nt][1] + b1;
            Ls[(row + 8) * 132 + col    ] = acc[mt][nt][2] + b0;
            Ls[(row + 8) * 132 + col + 1] = acc[mt][nt][3] + b1;
        }
    __syncthreads();

#pragma unroll
    for (int rr = 0; rr < 8; rr++) {
        int row = wid * 8 + rr;
        float v0 = Ls[row * 132 + lane], v1 = Ls[row * 132 + lane + 32];
        float v2 = Ls[row * 132 + lane + 64], v3 = Ls[row * 132 + lane + 96];
        float mx = fmaxf(fmaxf(v0, v1), fmaxf(v2, v3));
#pragma unroll
        for (int off = 16; off; off >>= 1) mx = fmaxf(mx, __shfl_xor_sync(0xffffffffu, mx, off));
        float s = expf(v0 - mx) + expf(v1 - mx) + expf(v2 - mx) + expf(v3 - mx);
#pragma unroll
        for (int off = 16; off; off >>= 1) s += __shfl_xor_sync(0xffffffffu, s, off);
        float lse = mx + logf(s);
        size_t base = (size_t)(bm + row) * VOCAB;
        out[base + lane]      = v0 - lse;
        out[base + lane + 32] = v1 - lse;
        out[base + lane + 64] = v2 - lse;
        out[base + lane + 96] = v3 - lse;
    }
}

// ---------------- launch ----------------
extern "C" void kernel_launch(void* const* d_in, const int* in_sizes, int n_in,
                              void* d_out, int out_size) {
    const float* inp = (const float*)d_in[0];
    const float* img = (const float*)d_in[1];
    const float* c1w = (const float*)d_in[2];
    const float* c1b = (const float*)d_in[3];
    const float* c2w = (const float*)d_in[4];
    const float* c2b = (const float*)d_in[5];
    const float* fw  = (const float*)d_in[6];
    const float* fb  = (const float*)d_in[7];
    const float* xhw = (const float*)d_in[8];
    const float* xhb = (const float*)d_in[9];
    const float* hhw = (const float*)d_in[10];
    const float* hhb = (const float*)d_in[11];
    const float* ow  = (const float*)d_in[12];
    const float* ob  = (const float*)d_in[13];
    float* out = (float*)d_out;

    cudaFuncSetAttribute(lstm_persistent, cudaFuncAttributeMaxDynamicSharedMemorySize, LSTM_SMEM);
    cudaFuncSetAttribute(out_logsoftmax_b, cudaFuncAttributeMaxDynamicSharedMemorySize, OUT_SMEM);
    cudaFuncSetAttribute(gemm_pre, cudaFuncAttributeMaxDynamicSharedMemorySize, GP_SMEM);
    cudaFuncSetAttribute(cnn_fused, cudaFuncAttributeMaxDynamicSharedMemorySize, CNN_SMEM);

    prep_all<<<PREP_BLOCKS, 256>>>(inp, hhw, xhw, ow, fw, xhb, hhb);            // 1
    cnn_fused<<<BATCH, 256, CNN_SMEM>>>(img, c1w, c1b, c2w, c2b);               // 2
    gemm_pre<<<64 + (G4 / 128) * ((T_LEN * BATCH) / 128), 256, GP_SMEM>>>(fb);  // 3
    lstm_persistent<<<128, 512, LSTM_SMEM>>>();                                  // 4 <- profiled
    out_logsoftmax_b<<<(T_LEN * BATCH) / 64, 256, OUT_SMEM>>>(ob, out);          // 5
}

// round 16
// speedup vs baseline: 1.0342x; 1.0342x over previous
#include <cuda_runtime.h>
#include <cuda_bf16.h>
#include <math.h>
#include <stdint.h>

#define T_LEN   64
#define BATCH   1024
#define VOCAB   128
#define HID     512
#define G4      2048
#define IMGFEAT 3600
#define KPAD    3648

// ---------------- helpers ----------------
__device__ __forceinline__ void cp16(uint32_t dst, const void* src) {
    size_t g = __cvta_generic_to_global(src);
    asm volatile("cp.async.cg.shared.global [%0], [%1], 16;" :: "r"(dst), "l"(g));
}
#define CP_COMMIT() asm volatile("cp.async.commit_group;" ::: "memory")
#define CP_WAIT(n)  asm volatile("cp.async.wait_group %0;" :: "n"(n) : "memory")

__device__ __forceinline__ uint32_t smem_u32(const void* p) {
    uint32_t a;
    asm("{ .reg .u64 t; cvta.to.shared.u64 t, %1; cvt.u32.u64 %0, t; }" : "=r"(a) : "l"(p));
    return a;
}

__device__ __forceinline__ float ftanh(float x) {
    float y;
    asm("tanh.approx.f32 %0, %1;" : "=f"(y) : "f"(x));
    return y;
}
__device__ __forceinline__ float fsig(float x) {
    return 0.5f * ftanh(0.5f * x) + 0.5f;
}

__device__ __forceinline__ uint32_t bf2_as_u32(__nv_bfloat162 v) {
    uint32_t u;
    memcpy(&u, &v, 4);
    return u;
}
__device__ __forceinline__ float2 u32_as_f2(uint32_t u) {
    __nv_bfloat162 v;
    memcpy(&v, &u, 4);
    return __bfloat1622float2(v);
}

__device__ __forceinline__ void mma_bf16(float c[4],
                                         uint32_t a0, uint32_t a1, uint32_t a2, uint32_t a3,
                                         uint32_t b0, uint32_t b1) {
    asm volatile(
        "mma.sync.aligned.m16n8k16.row.col.f32.bf16.bf16.f32 "
        "{%0,%1,%2,%3}, {%4,%5,%6,%7}, {%8,%9}, {%0,%1,%2,%3};"
        : "+f"(c[0]), "+f"(c[1]), "+f"(c[2]), "+f"(c[3])
        : "r"(a0), "r"(a1), "r"(a2), "r"(a3), "r"(b0), "r"(b1));
}

// ---- TMA 1D bulk copy + mbarrier ----
#define MBAR_INIT(mb, c)  asm volatile("mbarrier.init.shared.b64 [%0], %1;" :: "r"(mb), "r"(c) : "memory")
#define MBAR_EXPECT_TX(mb, bytes) \
    asm volatile("mbarrier.arrive.expect_tx.shared.b64 _, [%0], %1;" :: "r"(mb), "r"(bytes) : "memory")

__device__ __forceinline__ void bulk_g2s(uint32_t dst, const void* src, uint32_t bytes, uint32_t mbar) {
    asm volatile("cp.async.bulk.shared::cluster.global.mbarrier::complete_tx::bytes [%0], [%1], %2, [%3];"
                 :: "r"(dst), "l"(__cvta_generic_to_global((void*)src)), "r"(bytes), "r"(mbar) : "memory");
}

#define MBAR_WAIT(mb, par) do {                                                   \
    uint32_t _m = (mb), _p = (par), _d;                                           \
    asm volatile("{\n\t.reg .pred p;\n\t"                                         \
        "mbarrier.try_wait.parity.acquire.cta.shared::cta.b64 p, [%1], %2;\n\t"   \
        "selp.b32 %0, 1, 0, p;\n\t}" : "=r"(_d) : "r"(_m), "r"(_p) : "memory");   \
    if (!_d) {                                                                    \
        asm volatile("{\n\t.reg .pred P1;\n\t"                                    \
        "W_%=:\n\t"                                                               \
        "mbarrier.try_wait.parity.acquire.cta.shared::cta.b64 P1, [%0], %1, 0x989680;\n\t" \
        "@P1 bra.uni D_%=;\n\tbra.uni W_%=;\n\tD_%=:\n\t}"                        \
        :: "r"(_m), "r"(_p) : "memory");                                          \
    }                                                                             \
} while (0)

// ---------------- scratch ----------------
__device__ __nv_bfloat16 g_a2b[(size_t)BATCH * KPAD];
__device__ float g_e [BATCH * HID];
__device__ __nv_bfloat16 g_wt[(size_t)G4 * HID];
__device__ __nv_bfloat16 g_xt[(size_t)G4 * VOCAB];
__device__ __nv_bfloat16 g_owtb[VOCAB * HID];
__device__ __nv_bfloat16 g_fwt[(size_t)HID * KPAD];
__device__ float g_b4[G4];
__device__ __nv_bfloat16 g_hsb[(size_t)T_LEN * BATCH * HID];
__device__ uint32_t g_hswz[(size_t)T_LEN * 8 * 8 * 4096];
__device__ uint32_t g_xgt [(size_t)T_LEN * 8 * 16 * 8192];
__device__ unsigned g_barm[8];

// ---------------- prep + CNN fused (block-range dispatch) ----------------
// [0,1024)        cnn (one block per image)
// [1024,2048)     transpose hh  -> g_wt
// [2048,2304)     transpose xh  -> g_xt
// [2304,2368)     transpose ow  -> g_owtb
// [2368,4192)     transpose fw  -> g_fwt (zero-padded K)
// [4192,4200)     bias4
// 4200            flags
#define A1_CH  1156
#define SM_IMG 0
#define SM_A1  4356
#define SM_W1  13604
#define SM_B1  13676
#define SM_W2  13684
#define SM_B2  16884
#define CNN_SMEM (16900 * 4)
#define PREP_BLOCKS 4201

__global__ void __launch_bounds__(256, 1)
prep_cnn(const float* __restrict__ img,
         const float* __restrict__ c1w, const float* __restrict__ c1b,
         const float* __restrict__ c2w, const float* __restrict__ c2b,
         const float* __restrict__ hhw, const float* __restrict__ xhw,
         const float* __restrict__ ow,  const float* __restrict__ fw,
         const float* __restrict__ xhb, const float* __restrict__ hhb) {
    extern __shared__ float sf[];
    const int blk = blockIdx.x, tid = threadIdx.x;

    if (blk < 1024) {
        // ---------------- CNN path ----------------
        const int bb = blk;
        for (int i = tid; i < SM_A1 + 8 * A1_CH; i += 256) sf[i] = 0.f;
        for (int i = tid; i < 72; i += 256) sf[SM_W1 + i] = c1w[i];
        if (tid < 8) sf[SM_B1 + tid] = c1b[tid];
        for (int i = tid; i < 3200; i += 256) sf[SM_W2 + i] = c2w[i];
        if (tid < 16) sf[SM_B2 + tid] = c2b[tid];
        __syncthreads();

        const float* im = img + (size_t)bb * 4096;
        for (int i = tid; i < 1024; i += 256) {
            int r = i >> 4, c = (i & 15) * 4;
            float4 v = *(const float4*)&im[r * 64 + c];
            float* d = &sf[SM_IMG + (r + 1) * 66 + c + 1];
            d[0] = v.x; d[1] = v.y; d[2] = v.z; d[3] = v.w;
        }
        __syncthreads();

#pragma unroll
        for (int j = 0; j < 32; j++) {
            int idx = tid + j * 256;
            int px = idx & 31, py = (idx >> 5) & 31, oc = idx >> 10;
            const float* w = &sf[SM_W1 + oc * 9];
            float bias = sf[SM_B1 + oc];
            float m = -1e30f;
#pragma unroll
            for (int dy = 0; dy < 2; dy++)
#pragma unroll
            for (int dx = 0; dx < 2; dx++) {
                float acc = bias;
#pragma unroll
                for (int ky = 0; ky < 3; ky++)
#pragma unroll
                for (int kx = 0; kx < 3; kx++)
                    acc += sf[SM_IMG + (2 * py + dy + ky) * 66 + 2 * px + dx + kx] * w[ky * 3 + kx];
                m = fmaxf(m, fmaxf(acc, 0.f));
            }
            sf[SM_A1 + oc * A1_CH + (py + 1) * 34 + px + 1] = m;
        }
        __syncthreads();

        if (tid < 240) {
            int oc = tid / 15, py = tid % 15;
            float bias = sf[SM_B2 + oc];
            float m[15];
#pragma unroll
            for (int p = 0; p < 15; p++) m[p] = -1e30f;
#pragma unroll
            for (int dy = 0; dy < 2; dy++) {
                float conv[30];
#pragma unroll
                for (int ox = 0; ox < 30; ox++) conv[ox] = bias;
                for (int ic = 0; ic < 8; ic++) {
#pragma unroll
                    for (int ky = 0; ky < 5; ky++) {
                        const float* rp = &sf[SM_A1 + ic * A1_CH + (2 * py + dy + ky) * 34];
                        float r[34];
#pragma unroll
                        for (int xx = 0; xx < 34; xx++) r[xx] = rp[xx];
                        const float* wp = &sf[SM_W2 + (oc * 8 + ic) * 25 + ky * 5];
#pragma unroll
                        for (int kx = 0; kx < 5; kx++) {
                            float w = wp[kx];
#pragma unroll
                            for (int ox = 0; ox < 30; ox++) conv[ox] += r[ox + kx] * w;
                        }
                    }
                }
#pragma unroll
                for (int p = 0; p < 15; p++) {
                    float c0 = fmaxf(conv[2 * p], 0.f), c1 = fmaxf(conv[2 * p + 1], 0.f);
                    m[p] = fmaxf(m[p], fmaxf(c0, c1));
                }
            }
            size_t base = (size_t)bb * KPAD + oc * 225 + py * 15;
#pragma unroll
            for (int p = 0; p < 15; p++) g_a2b[base + p] = __float2bfloat16_rn(m[p]);
        }
        return;
    }

    // ---------------- transpose / misc paths ----------------
    float (*ts)[33] = (float(*)[33])sf;
    int x = tid & 31;
    int yr = tid >> 5;
    if (blk < 2048) {                        // hh: [512][2048] -> g_wt[2048][512]
        int b = blk - 1024;
        int bn = (b & 63) * 32, bk = (b >> 6) * 32;
#pragma unroll
        for (int i = 0; i < 32; i += 8)
            ts[yr + i][x] = hhw[(size_t)(bk + yr + i) * G4 + bn + x];
        __syncthreads();
#pragma unroll
        for (int i = 0; i < 32; i += 8)
            g_wt[(size_t)(bn + yr + i) * HID + bk + x] = __float2bfloat16_rn(ts[x][yr + i]);
    } else if (blk < 2304) {                 // xh: [128][2048] -> g_xt[2048][128]
        int b = blk - 2048;
        int bn = (b & 63) * 32, bk = (b >> 6) * 32;
#pragma unroll
        for (int i = 0; i < 32; i += 8)
            ts[yr + i][x] = xhw[(size_t)(bk + yr + i) * G4 + bn + x];
        __syncthreads();
#pragma unroll
        for (int i = 0; i < 32; i += 8)
            g_xt[(size_t)(bn + yr + i) * VOCAB + bk + x] = __float2bfloat16_rn(ts[x][yr + i]);
    } else if (blk < 2368) {                 // ow: [512][128] -> g_owtb[128][512]
        int b = blk - 2304;
        int bn = (b & 3) * 32, bk = (b >> 2) * 32;
#pragma unroll
        for (int i = 0; i < 32; i += 8)
            ts[yr + i][x] = ow[(size_t)(bk + yr + i) * VOCAB + bn + x];
        __syncthreads();
#pragma unroll
        for (int i = 0; i < 32; i += 8)
            g_owtb[(size_t)(bn + yr + i) * HID + bk + x] = __float2bfloat16_rn(ts[x][yr + i]);
    } else if (blk < 4192) {                 // fw: [3600][512] -> g_fwt[512][3648] pad 0
        int b = blk - 2368;
        int bn = (b & 15) * 32, bk = (b >> 4) * 32;
#pragma unroll
        for (int i = 0; i < 32; i += 8) {
            int k = bk + yr + i;
            ts[yr + i][x] = (k < IMGFEAT) ? fw[(size_t)k * HID + bn + x] : 0.f;
        }
        __syncthreads();
#pragma unroll
        for (int i = 0; i < 32; i += 8)
            g_fwt[(size_t)(bn + yr + i) * KPAD + bk + x] = __float2bfloat16_rn(ts[x][yr + i]);
    } else if (blk < 4200) {
        int i = (blk - 4192) * 256 + tid;
        g_b4[i] = xhb[i] + hhb[i];
    } else {
        if (tid < 8) g_barm[tid] = 0;
    }
}

// ---------------- gemm_pre: imgfc (blk<64) + xg (blk>=64, inline f32->bf16) ----------------
#define IF_AS 36
#define IF_ABUF (128 * IF_AS)
#define IF_BBUF (64 * IF_AS)
#define XG_AS 68
#define GP_SMEM (2 * 128 * XG_AS * 4)

__global__ void __launch_bounds__(256, 1)
gemm_pre(const float* __restrict__ inp, const float* __restrict__ fb) {
    extern __shared__ uint32_t smu[];
    const int tid = threadIdx.x, lane = tid & 31, wid = tid >> 5;
    const int gq = lane >> 2, tq = lane & 3;

    if (blockIdx.x < 64) {
        uint32_t* As = smu;
        uint32_t* Bs = smu + 2 * IF_ABUF;
        const uint32_t a_u = smem_u32(As), b_u = smem_u32(Bs);
        const int wm = wid & 3, wn = wid >> 2;
        const int bm = (blockIdx.x >> 3) * 128, bn = (blockIdx.x & 7) * 64;

        float acc[2][4][4] = {};
        auto load_chunk = [&](int k0, int p) {
#pragma unroll
            for (int j = 0; j < 4; j++) {
                int idx = tid + j * 256;
                int r = idx >> 3, c4 = idx & 7;
                cp16(a_u + p * IF_ABUF * 4 + r * (IF_AS * 4) + c4 * 16,
                     g_a2b + (size_t)(bm + r) * KPAD + k0 + c4 * 8);
            }
#pragma unroll
            for (int j = 0; j < 2; j++) {
                int idx = tid + j * 256;
                int r = idx >> 3, c4 = idx & 7;
                cp16(b_u + p * IF_BBUF * 4 + r * (IF_AS * 4) + c4 * 16,
                     g_fwt + (size_t)(bn + r) * KPAD + k0 + c4 * 8);
            }
            CP_COMMIT();
        };

        const int NCH = KPAD / 64;
        load_chunk(0, 0);
        for (int c = 0; c < NCH; c++) {
            if (c + 1 < NCH) { load_chunk((c + 1) * 64, (c + 1) & 1); CP_WAIT(1); }
            else             { CP_WAIT(0); }
            __syncthreads();
            const uint32_t* Ab = As + (c & 1) * IF_ABUF;
            const uint32_t* Bb = Bs + (c & 1) * IF_BBUF;
#pragma unroll
            for (int ks = 0; ks < 4; ks++) {
                uint32_t afr[2][4];
#pragma unroll
                for (int mt = 0; mt < 2; mt++) {
                    int r0 = wm * 32 + mt * 16 + gq;
                    afr[mt][0] = Ab[(r0    ) * IF_AS + ks * 8 + tq    ];
                    afr[mt][1] = Ab[(r0 + 8) * IF_AS + ks * 8 + tq    ];
                    afr[mt][2] = Ab[(r0    ) * IF_AS + ks * 8 + tq + 4];
                    afr[mt][3] = Ab[(r0 + 8) * IF_AS + ks * 8 + tq + 4];
                }
#pragma unroll
                for (int nt = 0; nt < 4; nt++) {
                    int nrow = wn * 32 + nt * 8 + gq;
                    uint32_t b0 = Bb[nrow * IF_AS + ks * 8 + tq    ];
                    uint32_t b1 = Bb[nrow * IF_AS + ks * 8 + tq + 4];
#pragma unroll
                    for (int mt = 0; mt < 2; mt++)
                        mma_bf16(acc[mt][nt], afr[mt][0], afr[mt][1], afr[mt][2], afr[mt][3], b0, b1);
                }
            }
            __syncthreads();
        }

#pragma unroll
        for (int mt = 0; mt < 2; mt++)
#pragma unroll
            for (int nt = 0; nt < 4; nt++) {
                int n = bn + wn * 32 + nt * 8 + tq * 2;
                int m = bm + wm * 32 + mt * 16 + gq;
                float b0 = fb[n], b1 = fb[n + 1];
                g_e[(size_t)m * HID + n]           = fmaxf(acc[mt][nt][0] + b0, 0.f);
                g_e[(size_t)m * HID + n + 1]       = fmaxf(acc[mt][nt][1] + b1, 0.f);
                g_e[(size_t)(m + 8) * HID + n]     = fmaxf(acc[mt][nt][2] + b0, 0.f);
                g_e[(size_t)(m + 8) * HID + n + 1] = fmaxf(acc[mt][nt][3] + b1, 0.f);
            }
        return;
    }

    {
        uint32_t* As = smu;
        uint32_t* Bs = smu + 128 * XG_AS;
        const uint32_t b_u = smem_u32(Bs);
        const int wm = wid & 3, wn = wid >> 2;
        const int bb = (int)blockIdx.x - 64;
        const int bm = (bb >> 4) * 128, bn = (bb & 15) * 128;

        // B (weights, bf16) via cp.async
#pragma unroll
        for (int j = 0; j < 8; j++) {
            int idx = tid + j * 256;
            int r = idx >> 4, c4 = idx & 15;
            cp16(b_u + r * (XG_AS * 4) + c4 * 16, g_xt + (size_t)(bn + r) * VOCAB + c4 * 8);
        }
        CP_COMMIT();

        // A: read inp f32 directly, convert to bf16 in regs, STS
#pragma unroll
        for (int j = 0; j < 16; j++) {
            int idx = tid + j * 256;
            int r = idx >> 5, q = idx & 31;      // q = float4 idx within row
            float4 v = *(const float4*)&inp[(size_t)(bm + r) * VOCAB + q * 4];
            As[r * XG_AS + q * 2]     = bf2_as_u32(__float22bfloat162_rn(make_float2(v.x, v.y)));
            As[r * XG_AS + q * 2 + 1] = bf2_as_u32(__float22bfloat162_rn(make_float2(v.z, v.w)));
        }
        CP_WAIT(0);
        __syncthreads();

        float acc[2][8][4] = {};
#pragma unroll
        for (int ks = 0; ks < 8; ks++) {
            uint32_t afr[2][4];
#pragma unroll
            for (int mt = 0; mt < 2; mt++) {
                int r0 = wm * 32 + mt * 16 + gq;
                afr[mt][0] = As[(r0    ) * XG_AS + ks * 8 + tq    ];
                afr[mt][1] = As[(r0 + 8) * XG_AS + ks * 8 + tq    ];
                afr[mt][2] = As[(r0    ) * XG_AS + ks * 8 + tq + 4];
                afr[mt][3] = As[(r0 + 8) * XG_AS + ks * 8 + tq + 4];
            }
#pragma unroll
            for (int nt = 0; nt < 8; nt++) {
                int nrow = wn * 64 + nt * 8 + gq;
                uint32_t b0 = Bs[nrow * XG_AS + ks * 8 + tq    ];
                uint32_t b1 = Bs[nrow * XG_AS + ks * 8 + tq + 4];
#pragma unroll
                for (int mt = 0; mt < 2; mt++)
                    mma_bf16(acc[mt][nt], afr[mt][0], afr[mt][1], afr[mt][2], afr[mt][3], b0, b1);
            }
        }
        __syncthreads();

        uint32_t* St = smu;
        const int ns0 = (bn & 511) >> 5;
        const int g = bn >> 9;
#pragma unroll
        for (int mt = 0; mt < 2; mt++)
#pragma unroll
            for (int nt = 0; nt < 8; nt++) {
                int r = wm * 32 + mt * 16 + gq;
                int n = wn * 64 + nt * 8 + tq * 2;
                int ns_l = n >> 5;
                int jcol = (n & 31) >> 1;
                St[r * 64 + ns_l * 16 + jcol] =
                    bf2_as_u32(__float22bfloat162_rn(make_float2(acc[mt][nt][0], acc[mt][nt][1])));
                St[(r + 8) * 64 + ns_l * 16 + jcol] =
                    bf2_as_u32(__float22bfloat162_rn(make_float2(acc[mt][nt][2], acc[mt][nt][3])));
            }
        __syncthreads();

        const int t = bm >> 10, mg = (bm >> 7) & 7;
        const size_t blkbase = (size_t)(t * 8 + mg) * 16;
        for (int i = tid; i < 2048; i += 256) {
            int r = i >> 4, q = i & 15;
            int ns_l = q >> 2, k = q & 3;
            int kk = k ^ (r & 3);
            int gg = g ^ ((r & 4) >> 2);
            uint4 v = *(const uint4*)&St[r * 64 + ns_l * 16 + k * 4];
            *(uint4*)&g_xgt[(blkbase + ns0 + ns_l) * 8192 + r * 64 + gg * 16 + kk * 4] = v;
        }
    }
}

// ---------------- persistent LSTM (round-14 config: per-mg flag, early xg) ----------------
#define LSTM_SMEM (57856 * 4 + 48)

__global__ void __launch_bounds__(512, 1)
lstm_persistent() {
    extern __shared__ uint32_t S[];
    uint32_t* Bhh = S;
    uint32_t* Xgs = S + 33280;
    uint32_t* Abuf = S + 41472;
    const uint32_t xg_u = smem_u32(S + 33280);
    const uint32_t a_u0 = smem_u32(S + 41472);
    const uint32_t mb_u = smem_u32(S + 57856);

    const int tid = threadIdx.x, lane = tid & 31, wid = tid >> 5;
    const int wm = wid & 3, wn = wid >> 2;
    const int gq = lane >> 2, tq = lane & 3;
    const int blk = blockIdx.x;
    const int mg = blk >> 4, ns = blk & 15;
    const int m0 = mg * 128, n0 = ns * 32;
    const int kch = ns >> 1;

    for (int i = tid; i < 128 * 64; i += 512) {
        int row = i >> 6, c4 = i & 63;
        int g = row >> 5, n = row & 31;
        *(uint4*)((char*)Bhh + row * (260 * 4) + c4 * 16) =
            *(const uint4*)((const char*)(g_wt + (size_t)(g * HID + n0 + n) * HID) + c4 * 16);
    }
    if (tid == 0) {
#pragma unroll
        for (int s = 0; s < 4; s++) MBAR_INIT(mb_u + s * 8, 1);
        MBAR_INIT(mb_u + 32, 1);
    }

    float creg[2][2][2];
#pragma unroll
    for (int mt = 0; mt < 2; mt++)
#pragma unroll
        for (int h = 0; h < 2; h++) creg[mt][h][0] = creg[mt][h][1] = 0.f;

    __syncthreads();

    const int nn = n0 + wn * 8 + tq * 2;
    const int xr = gq << 2;
    int phA[4] = {0, 0, 0, 0};
    unsigned* flagp = &g_barm[mg];

    for (int t = 0; t < T_LEN; t++) {
        float acc[4][2][4];
#pragma unroll
        for (int g = 0; g < 4; g++)
#pragma unroll
            for (int mt = 0; mt < 2; mt++)
#pragma unroll
                for (int j = 0; j < 4; j++) acc[g][mt][j] = 0.f;

        const uint32_t* hsrc = g_hswz + (size_t)((t - 1) * 8 + mg) * 8 * 4096;

        if (tid == 0) {
            MBAR_EXPECT_TX(mb_u + 32, 32768u);
            bulk_g2s(xg_u, g_xgt + ((size_t)(t * 8 + mg) * 16 + ns) * 8192, 32768u, mb_u + 32);
        }

        if (t > 0) {
            if (tid == 0) {
                unsigned tgt = (unsigned)(16 * t), v;
                do {
                    asm volatile("ld.acquire.gpu.global.u32 %0, [%1];"
                                 : "=r"(v) : "l"(flagp) : "memory");
                } while (v < tgt);
#pragma unroll
                for (int s = 0; s < 3; s++) {
                    MBAR_EXPECT_TX(mb_u + s * 8, 16384u);
                    bulk_g2s(a_u0 + s * 16384, hsrc + s * 4096, 16384u, mb_u + s * 8);
                }
            }
            for (int c = 0; c < 8; c++) {
                if (c + 3 < 8 && tid == 0) {
                    int s2 = (c + 3) & 3;
                    MBAR_EXPECT_TX(mb_u + s2 * 8, 16384u);
                    bulk_g2s(a_u0 + s2 * 16384, hsrc + (c + 3) * 4096, 16384u, mb_u + s2 * 8);
                }
                int s = c & 3;
                MBAR_WAIT(mb_u + s * 8, phA[s] & 1);
                phA[s]++;

                const uint32_t* Apk = Abuf + s * 4096;
#pragma unroll
                for (int ks = 0; ks < 4; ks++) {
                    uint32_t afr[2][4];
#pragma unroll
                    for (int mt = 0; mt < 2; mt++) {
                        int r0 = wm * 32 + mt * 16 + gq;
                        afr[mt][0] = Apk[(r0    ) * 32 + ((ks * 8 + tq    ) ^ xr)];
                        afr[mt][1] = Apk[(r0 + 8) * 32 + ((ks * 8 + tq    ) ^ xr)];
                        afr[mt][2] = Apk[(r0    ) * 32 + ((ks * 8 + tq + 4) ^ xr)];
                        afr[mt][3] = Apk[(r0 + 8) * 32 + ((ks * 8 + tq + 4) ^ xr)];
                    }
                    const int kcol = c * 32 + ks * 8;
#pragma unroll
                    for (int g = 0; g < 4; g++) {
                        int nrow = g * 32 + wn * 8 + gq;
                        uint32_t b0 = Bhh[nrow * 260 + kcol + tq    ];
                        uint32_t b1 = Bhh[nrow * 260 + kcol + tq + 4];
#pragma unroll
                        for (int mt = 0; mt < 2; mt++)
                            mma_bf16(acc[g][mt], afr[mt][0], afr[mt][1], afr[mt][2], afr[mt][3], b0, b1);
                    }
                }
                __syncthreads();
            }
        }

        MBAR_WAIT(mb_u + 32, t & 1);

        float2 b4i = *(const float2*)&g_b4[0 * HID + nn];
        float2 b4f = *(const float2*)&g_b4[1 * HID + nn];
        float2 b4g = *(const float2*)&g_b4[2 * HID + nn];
        float2 b4o = *(const float2*)&g_b4[3 * HID + nn];
        __nv_bfloat16* hs_t = g_hsb + (size_t)t * BATCH * HID;
        uint32_t* hwz_t = g_hswz + (size_t)((t * 8 + mg) * 8 + kch) * 4096;
        const int ncol = wn * 4 + tq;
        const int cu = (nn >> 1) & 31;
#pragma unroll
        for (int mt = 0; mt < 2; mt++) {
#pragma unroll
            for (int half = 0; half < 2; half++) {
                int r = wm * 32 + mt * 16 + gq + half * 8;
                int m = m0 + r;
                float2 vi = u32_as_f2(Xgs[r * 64 + ((0 * 16 + ncol) ^ xr)]);
                float2 vf = u32_as_f2(Xgs[r * 64 + ((1 * 16 + ncol) ^ xr)]);
                float2 vg = u32_as_f2(Xgs[r * 64 + ((2 * 16 + ncol) ^ xr)]);
                float2 vo = u32_as_f2(Xgs[r * 64 + ((3 * 16 + ncol) ^ xr)]);
                float2 ev = make_float2(0.f, 0.f);
                if (t == 0) ev = *(const float2*)&g_e[(size_t)m * HID + nn];
                float2 hv;
#pragma unroll
                for (int e = 0; e < 2; e++) {
                    float ee = e ? ev.y : ev.x;
                    float gi = acc[0][mt][half * 2 + e] + (e ? b4i.y : b4i.x) + (e ? vi.y : vi.x) + ee;
                    float gf = acc[1][mt][half * 2 + e] + (e ? b4f.y : b4f.x) + (e ? vf.y : vf.x) + ee;
                    float gg = acc[2][mt][half * 2 + e] + (e ? b4g.y : b4g.x) + (e ? vg.y : vg.x) + ee;
                    float go = acc[3][mt][half * 2 + e] + (e ? b4o.y : b4o.x) + (e ? vo.y : vo.x) + ee;
                    float i_ = fsig(gi);
                    float f_ = fsig(gf);
                    float g_ = ftanh(gg);
                    float o_ = fsig(go);
                    float cn = f_ * creg[mt][half][e] + i_ * g_;
                    creg[mt][half][e] = cn;
                    float hn = o_ * ftanh(cn);
                    if (e) hv.y = hn; else hv.x = hn;
                }
                __nv_bfloat162 hb = __float22bfloat162_rn(hv);
                *(__nv_bfloat162*)&hs_t[(size_t)m * HID + nn] = hb;
                hwz_t[r * 32 + (cu ^ xr)] = bf2_as_u32(hb);
            }
        }

        __syncthreads();
        if (tid == 0 && t + 1 < T_LEN)
            asm volatile("red.release.gpu.global.add.u32 [%0], 1;" :: "l"(flagp) : "memory");
    }
}

// ---------------- out proj (bf16 mma) + fused log_softmax ----------------
#define O_AS 36
#define O_ABUF (64 * O_AS)
#define O_BBUF (128 * O_AS)
#define O_LSOFF (2 * O_ABUF + 2 * O_BBUF)
#define OUT_SMEM ((O_LSOFF + 64 * 132) * 4)
__global__ void __launch_bounds__(256, 1)
out_logsoftmax_b(const float* __restrict__ bias, float* __restrict__ out) {
    extern __shared__ uint32_t smu[];
    uint32_t* As = smu;
    uint32_t* Bs = smu + 2 * O_ABUF;
    float* Ls = (float*)(smu + O_LSOFF);
    const uint32_t a_u = smem_u32(As), b_u = smem_u32(Bs);
    const int tid = threadIdx.x, lane = tid & 31, wid = tid >> 5;
    const int wm = wid & 1, wn = wid >> 1;
    const int gq = lane >> 2, tq = lane & 3;
    const int bm = blockIdx.x * 64;

    float acc[2][4][4] = {};

    auto load_chunk = [&](int k0, int p) {
#pragma unroll
        for (int j = 0; j < 2; j++) {
            int idx = tid + j * 256;
            int r = idx >> 3, c4 = idx & 7;
            cp16(a_u + p * O_ABUF * 4 + r * (O_AS * 4) + c4 * 16,
                 g_hsb + (size_t)(bm + r) * HID + k0 + c4 * 8);
        }
#pragma unroll
        for (int j = 0; j < 4; j++) {
            int idx = tid + j * 256;
            int r = idx >> 3, c4 = idx & 7;
            cp16(b_u + p * O_BBUF * 4 + r * (O_AS * 4) + c4 * 16,
                 g_owtb + (size_t)r * HID + k0 + c4 * 8);
        }
        CP_COMMIT();
    };

    load_chunk(0, 0);
    for (int c = 0; c < 8; c++) {
        if (c + 1 < 8) { load_chunk((c + 1) * 64, (c + 1) & 1); CP_WAIT(1); }
        else           { CP_WAIT(0); }
        __syncthreads();
        const uint32_t* Ab = As + (c & 1) * O_ABUF;
        const uint32_t* Bb = Bs + (c & 1) * O_BBUF;
#pragma unroll
        for (int ks = 0; ks < 4; ks++) {
            uint32_t afr[2][4];
#pragma unroll
            for (int mt = 0; mt < 2; mt++) {
                int r0 = wm * 32 + mt * 16 + gq;
                afr[mt][0] = Ab[(r0    ) * O_AS + ks * 8 + tq    ];
                afr[mt][1] = Ab[(r0 + 8) * O_AS + ks * 8 + tq    ];
                afr[mt][2] = Ab[(r0    ) * O_AS + ks * 8 + tq + 4];
                afr[mt][3] = Ab[(r0 + 8) * O_AS + ks * 8 + tq + 4];
            }
#pragma unroll
            for (int nt = 0; nt < 4; nt++) {
                int nrow = wn * 32 + nt * 8 + gq;
                uint32_t b0 = Bb[nrow * O_AS + ks * 8 + tq    ];
                uint32_t b1 = Bb[nrow * O_AS + ks * 8 + tq + 4];
#pragma unroll
                for (int mt = 0; mt < 2; mt++)
                    mma_bf16(acc[mt][nt], afr[mt][0], afr[mt][1], afr[mt][2], afr[mt][3], b0, b1);
            }
        }
        __syncthreads();
    }

#pragma unroll
    for (int mt = 0; mt < 2; mt++)
#pragma unroll
        for (int nt = 0; nt < 4; nt++) {
            int row = wm * 32 + mt * 16 + gq;
            int col = wn * 32 + nt * 8 + tq * 2;
            float b0 = bias[col], b1 = bias[col + 1];
            Ls[(row    ) * 132 + col    ] = acc[mt][nt][0] + b0;
            Ls[(row    ) * 132 + col + 1] = acc[mt][nt][1] + b1;
            Ls[(row + 8) * 132 + col    ] = acc[mt][nt][2] + b0;
            Ls[(row + 8) * 132 + col + 1] = acc[mt][nt][3] + b1;
        }
    __syncthreads();

#pragma unroll
    for (int rr = 0; rr < 8; rr++) {
        int row = wid * 8 + rr;
        float v0 = Ls[row * 132 + lane], v1 = Ls[row * 132 + lane + 32];
        float v2 = Ls[row * 132 + lane + 64], v3 = Ls[row * 132 + lane + 96];
        float mx = fmaxf(fmaxf(v0, v1), fmaxf(v2, v3));
#pragma unroll
        for (int off = 16; off; off >>= 1) mx = fmaxf(mx, __shfl_xor_sync(0xffffffffu, mx, off));
        float s = expf(v0 - mx) + expf(v1 - mx) + expf(v2 - mx) + expf(v3 - mx);
#pragma unroll
        for (int off = 16; off; off >>= 1) s += __shfl_xor_sync(0xffffffffu, s, off);
        float lse = mx + logf(s);
        size_t base = (size_t)(bm + row) * VOCAB;
        out[base + lane]      = v0 - lse;
        out[base + lane + 32] = v1 - lse;
        out[base + lane + 64] = v2 - lse;
        out[base + lane + 96] = v3 - lse;
    }
}

// ---------------- launch ----------------
extern "C" void kernel_launch(void* const* d_in, const int* in_sizes, int n_in,
                              void* d_out, int out_size) {
    const float* inp = (const float*)d_in[0];
    const float* img = (const float*)d_in[1];
    const float* c1w = (const float*)d_in[2];
    const float* c1b = (const float*)d_in[3];
    const float* c2w = (const float*)d_in[4];
    const float* c2b = (const float*)d_in[5];
    const float* fw  = (const float*)d_in[6];
    const float* fb  = (const float*)d_in[7];
    const float* xhw = (const float*)d_in[8];
    const float* xhb = (const float*)d_in[9];
    const float* hhw = (const float*)d_in[10];
    const float* hhb = (const float*)d_in[11];
    const float* ow  = (const float*)d_in[12];
    const float* ob  = (const float*)d_in[13];
    float* out = (float*)d_out;

    cudaFuncSetAttribute(lstm_persistent, cudaFuncAttributeMaxDynamicSharedMemorySize, LSTM_SMEM);
    cudaFuncSetAttribute(out_logsoftmax_b, cudaFuncAttributeMaxDynamicSharedMemorySize, OUT_SMEM);
    cudaFuncSetAttribute(gemm_pre, cudaFuncAttributeMaxDynamicSharedMemorySize, GP_SMEM);
    cudaFuncSetAttribute(prep_cnn, cudaFuncAttributeMaxDynamicSharedMemorySize, CNN_SMEM);

    prep_cnn<<<PREP_BLOCKS, 256, CNN_SMEM>>>(img, c1w, c1b, c2w, c2b,
                                             hhw, xhw, ow, fw, xhb, hhb);        // 1
    gemm_pre<<<64 + (G4 / 128) * ((T_LEN * BATCH) / 128), 256, GP_SMEM>>>(inp, fb); // 2
    lstm_persistent<<<128, 512, LSTM_SMEM>>>();                                   // 3
    out_logsoftmax_b<<<(T_LEN * BATCH) / 64, 256, OUT_SMEM>>>(ob, out);            // 4
}